// round 11
// baseline (speedup 1.0000x reference)
#include <cuda_runtime.h>

#define NB   32
#define CC   49
#define HW   81
#define PITCH 84          // row pitch everywhere (floats, 16B-aligned rows)
#define Q4   21           // PITCH/4
#define OO   24
#define KK   7
#define DD   49
#define DD2  54           // ms rows incl zero pad rows 49..53 (fk dd overreach)
#define GP   52           // gs row pitch (c-dim, mult of 4)
#define NT   128          // 4 warps; 5 CTAs/SM -> 102-reg budget, ~20.8 warps/SM

// scratch layout [n][c][o][PITCH] so the o-reduction reads contiguous chunks
__device__ float  g_scr[(size_t)NB * CC * OO * PITCH];   // 12.6 MB
__device__ float  g_pre[(size_t)NB * CC * PITCH];        // 527 KB pre-norm (pitched)
__device__ float2 g_part[CC * NB];                       // per (c,n) partial sums

typedef unsigned long long ull;

__device__ __forceinline__ void ffma2(ull& d, ull a, ull b) {
    asm("fma.rn.f32x2 %0, %1, %2, %0;" : "+l"(d) : "l"(a), "l"(b));
}
__device__ __forceinline__ ull pack2(float x) {
    ull r;
    unsigned u = __float_as_uint(x);
    asm("mov.b64 %0, {%1, %1};" : "=l"(r) : "r"(u));
    return r;
}
__device__ __forceinline__ float hadd2(ull v) {
    float2 f = *(float2*)&v;
    return f.x + f.y;
}

__global__ __launch_bounds__(NT, 5) void k_main(const float* __restrict__ x,
                                                const float* __restrict__ w) {
    const int n = blockIdx.x / OO;
    const int o = blockIdx.x % OO;
    __shared__ __align__(16) float ms[DD2 * PITCH];  // 18144 B (rows 49-53 zero)
    __shared__ __align__(16) float xa[DD * PITCH];   // 16464 B (total 33.8KB)
    float* const xs = xa;
    float* const gs = xa;   // after fk reads xs, xa is reused as gs[dd][c] (54*52<=4116)
    const int tid = threadIdx.x;

    // ---- load x[n] (pitch 84, 49 rows); zero pads; zero ms rows 49-53 ----
    const float* xn = x + (size_t)n * CC * HW;
    for (int i = tid; i < CC * HW; i += NT) {
        int c = i / HW, hw = i - c * HW;
        xs[c * PITCH + hw] = xn[i];
    }
    for (int i = tid; i < CC * 3; i += NT) {
        int c = i / 3;
        xs[c * PITCH + HW + (i - c * 3)] = 0.f;
    }
    for (int i = tid; i < 5 * PITCH; i += NT) ms[DD * PITCH + i] = 0.f;
    ull wl2[KK];
#pragma unroll
    for (int k = 0; k < KK; k++) wl2[k] = pack2(w[o * KK + k]);
    __syncthreads();

    // ---- depth conv along d: sliding window in regs, both-side guarded ----
    // 126 threads: 3 d-segments x 42 hw-pairs. Bias cancels in softmax.
    if (tid < 126) {
        int seg = tid / 42;
        int p = tid - seg * 42;
        int d0 = seg * 17;
        int dlen = (seg == 2) ? 15 : 17;
        ull win[KK];
#pragma unroll
        for (int k = 0; k < KK; k++) {
            int r = d0 - 3 + k;
            win[k] = (r >= 0 && r < DD) ? *(const ull*)(xs + r * PITCH + 2 * p) : 0ull;
        }
        for (int d = d0; d < d0 + dlen; d++) {
            ull acc = 0ull;
#pragma unroll
            for (int k = 0; k < KK; k++) ffma2(acc, wl2[k], win[k]);
            *(ull*)(ms + d * PITCH + 2 * p) = acc;
#pragma unroll
            for (int k = 0; k < KK - 1; k++) win[k] = win[k + 1];
            int r = d + 4;
            win[6] = (r < DD) ? *(const ull*)(xs + r * PITCH + 2 * p) : 0ull;
        }
    }
    __syncthreads();

    // ---- softmax over hw per row d: warp per row (4 warps) ----
    const int wid = tid >> 5, lane = tid & 31;
    for (int d = wid; d < DD; d += 4) {
        float* row = ms + d * PITCH;
        float m0 = row[lane];
        float m1 = row[lane + 32];
        float m2 = (lane < 17) ? row[lane + 64] : -1e30f;
        float mx = fmaxf(m0, fmaxf(m1, m2));
#pragma unroll
        for (int s = 16; s; s >>= 1) mx = fmaxf(mx, __shfl_xor_sync(~0u, mx, s));
        float e0 = __expf(m0 - mx);
        float e1 = __expf(m1 - mx);
        float e2 = (lane < 17) ? __expf(m2 - mx) : 0.f;
        float sm = e0 + e1 + e2;
#pragma unroll
        for (int s = 16; s; s >>= 1) sm += __shfl_xor_sync(~0u, sm, s);
        float inv = 1.f / sm;
        row[lane]      = e0 * inv;
        row[lane + 32] = e1 * inv;
        if (lane < 17) row[lane + 64] = e2 * inv;
        if (lane < 3)  row[HW + lane] = 0.f;   // pads stay zero
    }
    __syncthreads();

    // ---- fk = X * M^T: 117 tiles of 4c x 6dd; all operands LDS.128 ----
    // c = cg + 12i (max 48, duplicate writes carry identical values)
    // dd = dg + 9j (max 53; ms rows 49-53 zero -> gs zero, never read)
    ull a[4][6];
    int cg = 0, dg = 0;
    if (tid < 117) {
        cg = tid / 9; dg = tid - cg * 9;
#pragma unroll
        for (int i = 0; i < 4; i++)
#pragma unroll
            for (int j = 0; j < 6; j++) a[i][j] = 0ull;
        const float* xp = xs + cg * PITCH;
        const float* mp = ms + dg * PITCH;
#pragma unroll 1
        for (int p = 0; p < Q4; p++) {
            ulonglong2 X0 = *(const ulonglong2*)(xp);
            ulonglong2 X1 = *(const ulonglong2*)(xp + 12 * PITCH);
            ulonglong2 X2 = *(const ulonglong2*)(xp + 24 * PITCH);
            ulonglong2 X3 = *(const ulonglong2*)(xp + 36 * PITCH);
            {
                ulonglong2 B0 = *(const ulonglong2*)(mp);
                ulonglong2 B1 = *(const ulonglong2*)(mp +  9 * PITCH);
                ulonglong2 B2 = *(const ulonglong2*)(mp + 18 * PITCH);
                ffma2(a[0][0], X0.x, B0.x); ffma2(a[0][1], X0.x, B1.x); ffma2(a[0][2], X0.x, B2.x);
                ffma2(a[1][0], X1.x, B0.x); ffma2(a[1][1], X1.x, B1.x); ffma2(a[1][2], X1.x, B2.x);
                ffma2(a[2][0], X2.x, B0.x); ffma2(a[2][1], X2.x, B1.x); ffma2(a[2][2], X2.x, B2.x);
                ffma2(a[3][0], X3.x, B0.x); ffma2(a[3][1], X3.x, B1.x); ffma2(a[3][2], X3.x, B2.x);
                ffma2(a[0][0], X0.y, B0.y); ffma2(a[0][1], X0.y, B1.y); ffma2(a[0][2], X0.y, B2.y);
                ffma2(a[1][0], X1.y, B0.y); ffma2(a[1][1], X1.y, B1.y); ffma2(a[1][2], X1.y, B2.y);
                ffma2(a[2][0], X2.y, B0.y); ffma2(a[2][1], X2.y, B1.y); ffma2(a[2][2], X2.y, B2.y);
                ffma2(a[3][0], X3.y, B0.y); ffma2(a[3][1], X3.y, B1.y); ffma2(a[3][2], X3.y, B2.y);
            }
            {
                ulonglong2 B3 = *(const ulonglong2*)(mp + 27 * PITCH);
                ulonglong2 B4 = *(const ulonglong2*)(mp + 36 * PITCH);
                ulonglong2 B5 = *(const ulonglong2*)(mp + 45 * PITCH);
                ffma2(a[0][3], X0.x, B3.x); ffma2(a[0][4], X0.x, B4.x); ffma2(a[0][5], X0.x, B5.x);
                ffma2(a[1][3], X1.x, B3.x); ffma2(a[1][4], X1.x, B4.x); ffma2(a[1][5], X1.x, B5.x);
                ffma2(a[2][3], X2.x, B3.x); ffma2(a[2][4], X2.x, B4.x); ffma2(a[2][5], X2.x, B5.x);
                ffma2(a[3][3], X3.x, B3.x); ffma2(a[3][4], X3.x, B4.x); ffma2(a[3][5], X3.x, B5.x);
                ffma2(a[0][3], X0.y, B3.y); ffma2(a[0][4], X0.y, B4.y); ffma2(a[0][5], X0.y, B5.y);
                ffma2(a[1][3], X1.y, B3.y); ffma2(a[1][4], X1.y, B4.y); ffma2(a[1][5], X1.y, B5.y);
                ffma2(a[2][3], X2.y, B3.y); ffma2(a[2][4], X2.y, B4.y); ffma2(a[2][5], X2.y, B5.y);
                ffma2(a[3][3], X3.y, B3.y); ffma2(a[3][4], X3.y, B4.y); ffma2(a[3][5], X3.y, B5.y);
            }
            xp += 4; mp += 4;
        }
    }
    __syncthreads();           // all xs reads done -> xa becomes gs
    if (tid < 117) {
#pragma unroll
        for (int j = 0; j < 6; j++) {
            int dd = dg + 9 * j;
#pragma unroll
            for (int i = 0; i < 4; i++) {
                float s = hadd2(a[i][j]);
                s = (s >= 0.f) ? s : 0.01f * s;   // leaky (mask>0 => sign preserved)
                gs[dd * GP + cg + 12 * i] = s;    // dups/zero-rows write consistent values
            }
        }
    }
    __syncthreads();

    // ---- contrib[c][hw] = sum_dd gs[dd][c] * ms[dd][hw]; 4c x 12hw, LDS.128 ----
    if (tid < 91) {
        int pr = tid / 7, qg = tid - pr * 7;
        int c0 = 4 * pr;
        ull A[4][6];
#pragma unroll
        for (int i = 0; i < 4; i++)
#pragma unroll
            for (int k = 0; k < 6; k++) A[i][k] = 0ull;
        const float* gp = gs + c0;
        const float* mq = ms + qg * 12;
#pragma unroll 2
        for (int dd = 0; dd < DD; dd++) {
            float4 g4 = *(const float4*)(gp);
            ull p0 = pack2(g4.x), p1 = pack2(g4.y), p2 = pack2(g4.z), p3 = pack2(g4.w);
            {
                ulonglong2 v0 = *(const ulonglong2*)(mq);
                ffma2(A[0][0], p0, v0.x); ffma2(A[0][1], p0, v0.y);
                ffma2(A[1][0], p1, v0.x); ffma2(A[1][1], p1, v0.y);
                ffma2(A[2][0], p2, v0.x); ffma2(A[2][1], p2, v0.y);
                ffma2(A[3][0], p3, v0.x); ffma2(A[3][1], p3, v0.y);
            }
            {
                ulonglong2 v1 = *(const ulonglong2*)(mq + 4);
                ffma2(A[0][2], p0, v1.x); ffma2(A[0][3], p0, v1.y);
                ffma2(A[1][2], p1, v1.x); ffma2(A[1][3], p1, v1.y);
                ffma2(A[2][2], p2, v1.x); ffma2(A[2][3], p2, v1.y);
                ffma2(A[3][2], p3, v1.x); ffma2(A[3][3], p3, v1.y);
            }
            {
                ulonglong2 v2 = *(const ulonglong2*)(mq + 8);
                ffma2(A[0][4], p0, v2.x); ffma2(A[0][5], p0, v2.y);
                ffma2(A[1][4], p1, v2.x); ffma2(A[1][5], p1, v2.y);
                ffma2(A[2][4], p2, v2.x); ffma2(A[2][5], p2, v2.y);
                ffma2(A[3][4], p3, v2.x); ffma2(A[3][5], p3, v2.y);
            }
            gp += GP; mq += PITCH;
        }
#pragma unroll
        for (int i = 0; i < 4; i++) {
            int c = c0 + i;
            if (c < CC) {
                float* dst = g_scr + ((size_t)(n * CC + c) * OO + o) * PITCH + qg * 12;
                ulonglong2 w0 = {A[i][0], A[i][1]};
                ulonglong2 w1 = {A[i][2], A[i][3]};
                ulonglong2 w2 = {A[i][4], A[i][5]};   // ms pads zero -> pad cols zero
                *(ulonglong2*)(dst)     = w0;
                *(ulonglong2*)(dst + 4) = w1;
                *(ulonglong2*)(dst + 8) = w2;
            }
        }
    }
}

// per-(n,c): residual + sum over o (float4, 24-deep MLP), partial stats
__global__ __launch_bounds__(32) void k_sum(const float* __restrict__ x) {
    const int nc = blockIdx.x;              // n*CC + c
    const int q = threadIdx.x;              // 0..31, 21 active float4 columns
    float4 v = {0.f, 0.f, 0.f, 0.f};
    if (q < Q4) {
        const float4* base = (const float4*)g_scr + ((size_t)nc * OO) * Q4 + q;
#pragma unroll
        for (int o = 0; o < OO; o++) {
            float4 t = base[o * Q4];
            v.x += t.x; v.y += t.y; v.z += t.z; v.w += t.w;
        }
        const float* xr = x + (size_t)nc * HW + 4 * q;
        int rem = HW - 4 * q;
        if (rem > 0) v.x += xr[0];
        if (rem > 1) v.y += xr[1];
        if (rem > 2) v.z += xr[2];
        if (rem > 3) v.w += xr[3];
        ((float4*)g_pre)[(size_t)nc * Q4 + q] = v;
    }
    float s  = v.x + v.y + v.z + v.w;
    float s2 = v.x * v.x + v.y * v.y + v.z * v.z + v.w * v.w;
#pragma unroll
    for (int sh = 16; sh; sh >>= 1) {
        s  += __shfl_xor_sync(~0u, s,  sh);
        s2 += __shfl_xor_sync(~0u, s2, sh);
    }
    if (q == 0) {
        int n = nc / CC, c = nc - n * CC;
        g_part[c * NB + n] = make_float2(s, s2);
    }
}

// block per channel: reduce partials -> scale/shift, then normalize
__global__ __launch_bounds__(256) void k_norm(const float* __restrict__ gamma,
                                              const float* __restrict__ beta,
                                              float* __restrict__ out) {
    const int c = blockIdx.x;
    const int tid = threadIdx.x;
    __shared__ float2 ss;
    if (tid < 32) {
        float2 p = g_part[c * NB + tid];
        float s = p.x, s2 = p.y;
#pragma unroll
        for (int sh = 16; sh; sh >>= 1) {
            s  += __shfl_xor_sync(~0u, s,  sh);
            s2 += __shfl_xor_sync(~0u, s2, sh);
        }
        if (tid == 0) {
            const float invM = 1.f / (NB * HW);
            float mean = s * invM;
            float var  = s2 * invM - mean * mean;
            float sc = gamma[c] * rsqrtf(var + 1e-5f);
            ss = make_float2(sc, beta[c] - mean * sc);
        }
    }
    __syncthreads();
    float2 f = ss;
    for (int i = tid; i < NB * HW; i += 256) {
        int n = i / HW, hw = i - n * HW;
        float v = g_pre[(size_t)(n * CC + c) * PITCH + hw];
        out[(size_t)(n * CC + c) * HW + hw] = v * f.x + f.y;
    }
}

extern "C" void kernel_launch(void* const* d_in, const int* in_sizes, int n_in,
                              void* d_out, int out_size) {
    const float* x     = (const float*)d_in[0];
    const float* w     = (const float*)d_in[1];
    // d_in[2] = conv_b: unused (constant per softmax row, cancels)
    const float* gamma = (const float*)d_in[3];
    const float* beta  = (const float*)d_in[4];
    float* out = (float*)d_out;

    k_main<<<NB * OO, NT>>>(x, w);
    k_sum<<<NB * CC, 32>>>(x);
    k_norm<<<CC, 256>>>(gamma, beta, out);
}

// round 12
// speedup vs baseline: 1.2600x; 1.2600x over previous
#include <cuda_runtime.h>

#define NB   32
#define CC   49
#define HW   81
#define PITCH 84          // row pitch everywhere (floats, 16B-aligned rows)
#define Q4   21           // PITCH/4
#define OO   24
#define KK   7
#define DD   49
#define GP   52           // gs row pitch (c-dim, mult of 4)
#define NT   96           // 3 warps; cap 6 CTAs/SM -> single wave (768 <= 888)

// scratch layout [n][c][o][PITCH] so the o-reduction reads contiguous chunks
__device__ float  g_scr[(size_t)NB * CC * OO * PITCH];   // 12.6 MB
__device__ float  g_pre[(size_t)NB * CC * PITCH];        // 527 KB pre-norm (pitched)
__device__ float2 g_part[CC * NB];                       // per (c,n) partial sums

typedef unsigned long long ull;

__device__ __forceinline__ void ffma2(ull& d, ull a, ull b) {
    asm("fma.rn.f32x2 %0, %1, %2, %0;" : "+l"(d) : "l"(a), "l"(b));
}
__device__ __forceinline__ ull pack2(float x) {
    ull r;
    unsigned u = __float_as_uint(x);
    asm("mov.b64 %0, {%1, %1};" : "=l"(r) : "r"(u));
    return r;
}
__device__ __forceinline__ float hadd2(ull v) {
    float2 f = *(float2*)&v;
    return f.x + f.y;
}

__global__ __launch_bounds__(NT, 6) void k_main(const float* __restrict__ x,
                                                const float* __restrict__ w) {
    const int n = blockIdx.x / OO;
    const int o = blockIdx.x % OO;
    __shared__ __align__(16) float ms[DD * PITCH];   // 16464 B
    __shared__ __align__(16) float xa[DD * PITCH];   // 16464 B (total 32.9KB)
    float* const xs = xa;
    float* const gs = xa;   // after fk reads xs, xa is reused as gs[dd][c]
    const int tid = threadIdx.x;

    // ---- load x[n] (pitch 84, 49 rows); zero pad cols 81-83 ----
    const float* xn = x + (size_t)n * CC * HW;
    for (int i = tid; i < CC * HW; i += NT) {
        int c = i / HW, hw = i - c * HW;
        xs[c * PITCH + hw] = xn[i];
    }
    for (int i = tid; i < CC * 3; i += NT) {
        int c = i / 3;
        xs[c * PITCH + HW + (i - c * 3)] = 0.f;
    }
    ull wl2[KK];
#pragma unroll
    for (int k = 0; k < KK; k++) wl2[k] = pack2(w[o * KK + k]);
    __syncthreads();

    // ---- depth conv along d: sliding window in regs, both-side guarded ----
    // 84 threads: 2 d-segments x 42 hw-pairs. Bias cancels in softmax.
    if (tid < 84) {
        int seg = tid / 42;
        int p = tid - seg * 42;
        int d0 = seg * 25;
        int dlen = seg ? 24 : 25;
        ull win[KK];
#pragma unroll
        for (int k = 0; k < KK; k++) {
            int r = d0 - 3 + k;
            win[k] = (r >= 0 && r < DD) ? *(const ull*)(xs + r * PITCH + 2 * p) : 0ull;
        }
        for (int d = d0; d < d0 + dlen; d++) {
            ull acc = 0ull;
#pragma unroll
            for (int k = 0; k < KK; k++) ffma2(acc, wl2[k], win[k]);
            *(ull*)(ms + d * PITCH + 2 * p) = acc;
#pragma unroll
            for (int k = 0; k < KK - 1; k++) win[k] = win[k + 1];
            int r = d + 4;
            win[6] = (r < DD) ? *(const ull*)(xs + r * PITCH + 2 * p) : 0ull;
        }
    }
    __syncthreads();

    // ---- softmax over hw per row d: warp per row (exactly 3 warps) ----
    const int wid = tid >> 5, lane = tid & 31;
    for (int d = wid; d < DD; d += 3) {
        float* row = ms + d * PITCH;
        float m0 = row[lane];
        float m1 = row[lane + 32];
        float m2 = (lane < 17) ? row[lane + 64] : -1e30f;
        float mx = fmaxf(m0, fmaxf(m1, m2));
#pragma unroll
        for (int s = 16; s; s >>= 1) mx = fmaxf(mx, __shfl_xor_sync(~0u, mx, s));
        float e0 = __expf(m0 - mx);
        float e1 = __expf(m1 - mx);
        float e2 = (lane < 17) ? __expf(m2 - mx) : 0.f;
        float sm = e0 + e1 + e2;
#pragma unroll
        for (int s = 16; s; s >>= 1) sm += __shfl_xor_sync(~0u, sm, s);
        float inv = 1.f / sm;
        row[lane]      = e0 * inv;
        row[lane + 32] = e1 * inv;
        if (lane < 17) row[lane + 64] = e2 * inv;
        if (lane < 3)  row[HW + lane] = 0.f;   // pads stay zero
    }
    __syncthreads();

    // ---- fk = X * M^T: 91 tiles of 4c x 7dd; ALL operands via LDS.128 ----
    ull a[4][7];
    int cg = 0, dg = 0;
    if (tid < 91) {
        cg = tid / 7; dg = tid - cg * 7;
#pragma unroll
        for (int i = 0; i < 4; i++)
#pragma unroll
            for (int j = 0; j < 7; j++) a[i][j] = 0ull;
        const float* xp = xs + cg * PITCH;
        const float* mp = ms + dg * PITCH;
#pragma unroll 1
        for (int p = 0; p < Q4; p++) {
            ulonglong2 X0 = *(const ulonglong2*)(xp);
            ulonglong2 X1 = *(const ulonglong2*)(xp + 12 * PITCH);
            ulonglong2 X2 = *(const ulonglong2*)(xp + 24 * PITCH);
            ulonglong2 X3 = *(const ulonglong2*)(xp + 36 * PITCH);
            {
                ulonglong2 B0 = *(const ulonglong2*)(mp);
                ulonglong2 B1 = *(const ulonglong2*)(mp +  7 * PITCH);
                ulonglong2 B2 = *(const ulonglong2*)(mp + 14 * PITCH);
                ulonglong2 B3 = *(const ulonglong2*)(mp + 21 * PITCH);
                ffma2(a[0][0], X0.x, B0.x); ffma2(a[0][1], X0.x, B1.x); ffma2(a[0][2], X0.x, B2.x); ffma2(a[0][3], X0.x, B3.x);
                ffma2(a[1][0], X1.x, B0.x); ffma2(a[1][1], X1.x, B1.x); ffma2(a[1][2], X1.x, B2.x); ffma2(a[1][3], X1.x, B3.x);
                ffma2(a[2][0], X2.x, B0.x); ffma2(a[2][1], X2.x, B1.x); ffma2(a[2][2], X2.x, B2.x); ffma2(a[2][3], X2.x, B3.x);
                ffma2(a[3][0], X3.x, B0.x); ffma2(a[3][1], X3.x, B1.x); ffma2(a[3][2], X3.x, B2.x); ffma2(a[3][3], X3.x, B3.x);
                ffma2(a[0][0], X0.y, B0.y); ffma2(a[0][1], X0.y, B1.y); ffma2(a[0][2], X0.y, B2.y); ffma2(a[0][3], X0.y, B3.y);
                ffma2(a[1][0], X1.y, B0.y); ffma2(a[1][1], X1.y, B1.y); ffma2(a[1][2], X1.y, B2.y); ffma2(a[1][3], X1.y, B3.y);
                ffma2(a[2][0], X2.y, B0.y); ffma2(a[2][1], X2.y, B1.y); ffma2(a[2][2], X2.y, B2.y); ffma2(a[2][3], X2.y, B3.y);
                ffma2(a[3][0], X3.y, B0.y); ffma2(a[3][1], X3.y, B1.y); ffma2(a[3][2], X3.y, B2.y); ffma2(a[3][3], X3.y, B3.y);
            }
            {
                ulonglong2 B4 = *(const ulonglong2*)(mp + 28 * PITCH);
                ulonglong2 B5 = *(const ulonglong2*)(mp + 35 * PITCH);
                ulonglong2 B6 = *(const ulonglong2*)(mp + 42 * PITCH);
                ffma2(a[0][4], X0.x, B4.x); ffma2(a[0][5], X0.x, B5.x); ffma2(a[0][6], X0.x, B6.x);
                ffma2(a[1][4], X1.x, B4.x); ffma2(a[1][5], X1.x, B5.x); ffma2(a[1][6], X1.x, B6.x);
                ffma2(a[2][4], X2.x, B4.x); ffma2(a[2][5], X2.x, B5.x); ffma2(a[2][6], X2.x, B6.x);
                ffma2(a[3][4], X3.x, B4.x); ffma2(a[3][5], X3.x, B5.x); ffma2(a[3][6], X3.x, B6.x);
                ffma2(a[0][4], X0.y, B4.y); ffma2(a[0][5], X0.y, B5.y); ffma2(a[0][6], X0.y, B6.y);
                ffma2(a[1][4], X1.y, B4.y); ffma2(a[1][5], X1.y, B5.y); ffma2(a[1][6], X1.y, B6.y);
                ffma2(a[2][4], X2.y, B4.y); ffma2(a[2][5], X2.y, B5.y); ffma2(a[2][6], X2.y, B6.y);
                ffma2(a[3][4], X3.y, B4.y); ffma2(a[3][5], X3.y, B5.y); ffma2(a[3][6], X3.y, B6.y);
            }
            xp += 4; mp += 4;
        }
    }
    __syncthreads();           // all xs reads done -> xa becomes gs
    if (tid < 91) {
#pragma unroll
        for (int j = 0; j < 7; j++) {
            int dd = dg + 7 * j;
#pragma unroll
            for (int i = 0; i < 4; i++) {
                float s = hadd2(a[i][j]);
                s = (s >= 0.f) ? s : 0.01f * s;   // leaky (mask>0 => sign preserved)
                gs[dd * GP + cg + 12 * i] = s;    // duplicates write identical values
            }
        }
    }
    __syncthreads();

    // ---- contrib[c][hw] = sum_dd gs[dd][c] * ms[dd][hw]; 4c x 12hw, LDS.128 ----
    if (tid < 91) {
        int pr = tid / 7, qg = tid - pr * 7;
        int c0 = 4 * pr;
        ull A[4][6];
#pragma unroll
        for (int i = 0; i < 4; i++)
#pragma unroll
            for (int k = 0; k < 6; k++) A[i][k] = 0ull;
        const float* gp = gs + c0;
        const float* mq = ms + qg * 12;
#pragma unroll 2
        for (int dd = 0; dd < DD; dd++) {
            float4 g4 = *(const float4*)(gp);
            ull p0 = pack2(g4.x), p1 = pack2(g4.y), p2 = pack2(g4.z), p3 = pack2(g4.w);
            {
                ulonglong2 v0 = *(const ulonglong2*)(mq);
                ffma2(A[0][0], p0, v0.x); ffma2(A[0][1], p0, v0.y);
                ffma2(A[1][0], p1, v0.x); ffma2(A[1][1], p1, v0.y);
                ffma2(A[2][0], p2, v0.x); ffma2(A[2][1], p2, v0.y);
                ffma2(A[3][0], p3, v0.x); ffma2(A[3][1], p3, v0.y);
            }
            {
                ulonglong2 v1 = *(const ulonglong2*)(mq + 4);
                ffma2(A[0][2], p0, v1.x); ffma2(A[0][3], p0, v1.y);
                ffma2(A[1][2], p1, v1.x); ffma2(A[1][3], p1, v1.y);
                ffma2(A[2][2], p2, v1.x); ffma2(A[2][3], p2, v1.y);
                ffma2(A[3][2], p3, v1.x); ffma2(A[3][3], p3, v1.y);
            }
            {
                ulonglong2 v2 = *(const ulonglong2*)(mq + 8);
                ffma2(A[0][4], p0, v2.x); ffma2(A[0][5], p0, v2.y);
                ffma2(A[1][4], p1, v2.x); ffma2(A[1][5], p1, v2.y);
                ffma2(A[2][4], p2, v2.x); ffma2(A[2][5], p2, v2.y);
                ffma2(A[3][4], p3, v2.x); ffma2(A[3][5], p3, v2.y);
            }
            gp += GP; mq += PITCH;
        }
#pragma unroll
        for (int i = 0; i < 4; i++) {
            int c = c0 + i;
            if (c < CC) {
                float* dst = g_scr + ((size_t)(n * CC + c) * OO + o) * PITCH + qg * 12;
                ulonglong2 w0 = {A[i][0], A[i][1]};
                ulonglong2 w1 = {A[i][2], A[i][3]};
                ulonglong2 w2 = {A[i][4], A[i][5]};   // ms pads zero -> pad cols zero
                *(ulonglong2*)(dst)     = w0;
                *(ulonglong2*)(dst + 4) = w1;
                *(ulonglong2*)(dst + 8) = w2;
            }
        }
    }
}

// per-(n,c): residual + sum over o (float4, 24-deep MLP), partial stats
__global__ __launch_bounds__(32) void k_sum(const float* __restrict__ x) {
    const int nc = blockIdx.x;              // n*CC + c
    const int q = threadIdx.x;              // 0..31, 21 active float4 columns
    float4 v = {0.f, 0.f, 0.f, 0.f};
    if (q < Q4) {
        const float4* base = (const float4*)g_scr + ((size_t)nc * OO) * Q4 + q;
#pragma unroll
        for (int o = 0; o < OO; o++) {
            float4 t = base[o * Q4];
            v.x += t.x; v.y += t.y; v.z += t.z; v.w += t.w;
        }
        const float* xr = x + (size_t)nc * HW + 4 * q;
        int rem = HW - 4 * q;
        if (rem > 0) v.x += xr[0];
        if (rem > 1) v.y += xr[1];
        if (rem > 2) v.z += xr[2];
        if (rem > 3) v.w += xr[3];
        ((float4*)g_pre)[(size_t)nc * Q4 + q] = v;
    }
    float s  = v.x + v.y + v.z + v.w;
    float s2 = v.x * v.x + v.y * v.y + v.z * v.z + v.w * v.w;
#pragma unroll
    for (int sh = 16; sh; sh >>= 1) {
        s  += __shfl_xor_sync(~0u, s,  sh);
        s2 += __shfl_xor_sync(~0u, s2, sh);
    }
    if (q == 0) {
        int n = nc / CC, c = nc - n * CC;
        g_part[c * NB + n] = make_float2(s, s2);
    }
}

// one block per (n,c): redundantly reduce this channel's 32 partials, normalize 81 elems
__global__ __launch_bounds__(96) void k_norm(const float* __restrict__ gamma,
                                             const float* __restrict__ beta,
                                             float* __restrict__ out) {
    const int nc = blockIdx.x;
    const int c = nc % CC;
    const int tid = threadIdx.x;
    __shared__ float2 ss;
    if (tid < 32) {
        float2 p = g_part[c * NB + tid];
        float s = p.x, s2 = p.y;
#pragma unroll
        for (int sh = 16; sh; sh >>= 1) {
            s  += __shfl_xor_sync(~0u, s,  sh);
            s2 += __shfl_xor_sync(~0u, s2, sh);
        }
        if (tid == 0) {
            const float invM = 1.f / (NB * HW);
            float mean = s * invM;
            float var  = s2 * invM - mean * mean;
            float sc = gamma[c] * rsqrtf(var + 1e-5f);
            ss = make_float2(sc, beta[c] - mean * sc);
        }
    }
    __syncthreads();
    if (tid < HW) {
        float2 f = ss;
        float v = g_pre[(size_t)nc * PITCH + tid];
        out[(size_t)nc * HW + tid] = v * f.x + f.y;
    }
}

extern "C" void kernel_launch(void* const* d_in, const int* in_sizes, int n_in,
                              void* d_out, int out_size) {
    const float* x     = (const float*)d_in[0];
    const float* w     = (const float*)d_in[1];
    // d_in[2] = conv_b: unused (constant per softmax row, cancels)
    const float* gamma = (const float*)d_in[3];
    const float* beta  = (const float*)d_in[4];
    float* out = (float*)d_out;

    k_main<<<NB * OO, NT>>>(x, w);
    k_sum<<<NB * CC, 32>>>(x);
    k_norm<<<NB * CC, 96>>>(gamma, beta, out);
}